// round 1
// baseline (speedup 1.0000x reference)
#include <cuda_runtime.h>

#define Nn    6000
#define DEG   16
#define Mm    17          // DEG + 1
#define NT    16
#define MTt   10
#define NF    128
#define KT    160         // NT * MTt
#define NITER 10
#define THREADS 320
#define GEMM_ROWS 40
#define GEMM_SMEM ((KT * 129 + GEMM_ROWS * NF) * 4)

// Scratch (no allocations allowed): G = x @ F2^T, plus squared norms
__device__ float g_G[Nn * KT];
__device__ float g_xn[Nn];
__device__ float g_f2n[KT];

// ---------------------------------------------------------------------------
// Kernel 0: row norms of x and F2
// ---------------------------------------------------------------------------
__global__ void norms_kernel(const float* __restrict__ x,
                             const float* __restrict__ F2) {
    int idx = blockIdx.x * blockDim.x + threadIdx.x;
    if (idx < Nn) {
        const float4* r = (const float4*)(x + (size_t)idx * NF);
        float s = 0.f;
        #pragma unroll
        for (int i = 0; i < NF / 4; i++) {
            float4 v = r[i];
            s += v.x * v.x + v.y * v.y + v.z * v.z + v.w * v.w;
        }
        g_xn[idx] = s;
    } else if (idx < Nn + KT) {
        int c = idx - Nn;
        const float4* r = (const float4*)(F2 + (size_t)c * NF);
        float s = 0.f;
        #pragma unroll
        for (int i = 0; i < NF / 4; i++) {
            float4 v = r[i];
            s += v.x * v.x + v.y * v.y + v.z * v.z + v.w * v.w;
        }
        g_f2n[c] = s;
    }
}

// ---------------------------------------------------------------------------
// Kernel 1: G[n][kt] = sum_f x[n][f] * F2[kt][f]   (6000 x 160 x 128 GEMM)
// Block computes 40 rows x 160 cols; F2 fully staged in smem (stride 129 to
// kill the 32-way bank conflict a 128-float stride would cause).
// ---------------------------------------------------------------------------
__global__ __launch_bounds__(256, 2)
void gemm_kernel(const float* __restrict__ x, const float* __restrict__ F2) {
    extern __shared__ float sm[];
    float* sF2 = sm;                 // 160 x 129
    float* sX  = sm + KT * 129;      // 40 x 128
    int tid = threadIdx.x;
    int r0 = blockIdx.x * GEMM_ROWS;

    for (int i = tid; i < KT * NF; i += 256) {
        int r = i >> 7, f = i & 127;
        sF2[r * 129 + f] = F2[i];
    }
    for (int i = tid; i < GEMM_ROWS * NF; i += 256)
        sX[i] = x[(size_t)r0 * NF + i];
    __syncthreads();

    int tm = tid >> 5;   // 0..7  -> 5 rows each
    int tn = tid & 31;   // 0..31 -> 5 cols each
    float acc[5][5];
    #pragma unroll
    for (int i = 0; i < 5; i++)
        #pragma unroll
        for (int j = 0; j < 5; j++) acc[i][j] = 0.f;

    for (int f = 0; f < NF; f++) {
        float av[5], bv[5];
        #pragma unroll
        for (int i = 0; i < 5; i++) av[i] = sX[(tm * 5 + i) * NF + f];
        #pragma unroll
        for (int j = 0; j < 5; j++) bv[j] = sF2[(tn * 5 + j) * 129 + f];
        #pragma unroll
        for (int i = 0; i < 5; i++)
            #pragma unroll
            for (int j = 0; j < 5; j++) acc[i][j] += av[i] * bv[j];
    }
    #pragma unroll
    for (int i = 0; i < 5; i++) {
        int row = r0 + tm * 5 + i;
        #pragma unroll
        for (int j = 0; j < 5; j++)
            g_G[(size_t)row * KT + tn * 5 + j] = acc[i][j];
    }
}

// ---------------------------------------------------------------------------
// Kernel 2: main mirror-descent. One block per node, 320 threads, 16 templates.
// ---------------------------------------------------------------------------
struct SmemMain {
    float lt[Mm * KT];     // 2720
    float Mc[Mm * KT];     // (1-alpha)/REG * Mcost
    float T [Mm * KT];
    float Y1[Mm * KT];
    float C2[NT * MTt * MTt];
    float q [KT];
    float cc[KT];          // constC2
    float c1p[Mm];
    int   nbrs[Mm];
    int   dstl[Mm * DEG];
    unsigned mask[Mm];
};

__global__ __launch_bounds__(THREADS, 4)
void main_kernel(const int* __restrict__ dst, const float* __restrict__ C2g,
                 const float* __restrict__ alpha0, float* __restrict__ out) {
    extern __shared__ char smraw[];
    SmemMain& s = *reinterpret_cast<SmemMain*>(smraw);
    int n = blockIdx.x, tid = threadIdx.x;

    float a0 = alpha0[0];
    float alpha = 1.f / (1.f + __expf(-a0));
    float coefA = alpha * 10.f;            // alpha / REG
    float coefM = (1.f - alpha) * 10.f;    // (1-alpha) / REG

    // --- neighbor list + C2 staging ---
    if (tid < Mm) s.nbrs[tid] = (tid == 0) ? n : dst[n * DEG + tid - 1];
    for (int i = tid; i < NT * MTt * MTt; i += THREADS) s.C2[i] = C2g[i];
    __syncthreads();

    if (tid < Mm * DEG)
        s.dstl[tid] = dst[s.nbrs[tid >> 4] * DEG + (tid & 15)];
    __syncthreads();

    // --- adjacency bitmask: C1[a][b] = (nbrs[b] in dstl[a]) || (nbrs[a] in dstl[b]) ---
    if (tid < Mm) {
        int me = s.nbrs[tid];
        unsigned mrow = 0;
        for (int b = 0; b < Mm; b++) {
            int nb = s.nbrs[b];
            bool adj = false;
            #pragma unroll
            for (int j = 0; j < DEG; j++)
                adj = adj || (s.dstl[tid * DEG + j] == nb) ||
                             (s.dstl[b   * DEG + j] == me);
            if (adj) mrow |= (1u << b);
        }
        s.mask[tid] = mrow;
        s.c1p[tid]  = (float)__popc(mrow) * (1.f / (float)Mm);  // C1^2=C1, p=1/17
    }
    __syncthreads();

    // --- Mconst from precomputed G/norms; lt init (log p - log MT is row-const
    //     -> softmax-invariant -> 0) ---
    for (int i = tid; i < Mm * KT; i += THREADS) {
        int mi = i / KT, c = i - mi * KT;
        int row = s.nbrs[mi];
        float dot = g_G[(size_t)row * KT + c];
        s.Mc[i] = coefM * (g_xn[row] + g_f2n[c] - 2.f * dot);
        s.lt[i] = 0.f;
    }
    __syncthreads();

    // --- 10 mirror-descent iterations ---
    for (int it = 0; it < NITER; it++) {
        // softmax over t (recentering lt by row max: softmax-invariant)
        if (tid < Mm * NT) {
            int mi = tid >> 4, k = tid & 15;
            int base = mi * KT + k * MTt;
            float v[MTt];
            float mx = -1e30f;
            #pragma unroll
            for (int t = 0; t < MTt; t++) { v[t] = s.lt[base + t]; mx = fmaxf(mx, v[t]); }
            float ssum = 0.f;
            #pragma unroll
            for (int t = 0; t < MTt; t++) {
                float d = v[t] - mx;
                s.lt[base + t] = d;
                float e = __expf(d);
                v[t] = e; ssum += e;
            }
            float inv = (1.f / (float)Mm) / ssum;
            #pragma unroll
            for (int t = 0; t < MTt; t++) s.T[base + t] = v[t] * inv;
        }
        __syncthreads();

        // q[kt] = sum_m T[m][kt]
        if (tid < KT) {
            float sq = 0.f;
            #pragma unroll
            for (int mi = 0; mi < Mm; mi++) sq += s.T[mi * KT + tid];
            s.q[tid] = sq;
        }
        __syncthreads();

        // constC2[k][j] = sum_b q[k][b] * C2[k][j][b]^2
        if (tid < KT) {
            int k = tid / MTt, j = tid - k * MTt;
            const float* c2 = &s.C2[k * (MTt * MTt) + j * MTt];
            const float* qq = &s.q[k * MTt];
            float sc = 0.f;
            #pragma unroll
            for (int b = 0; b < MTt; b++) { float c = c2[b]; sc += qq[b] * c * c; }
            s.cc[tid] = sc;
        }
        // Y1[a][kt] = sum_{b: C1[a][b]=1} T[b][kt]   (sparse via bitmask)
        for (int i = tid; i < Mm * KT; i += THREADS) {
            int a = i / KT, c = i - a * KT;
            unsigned msk = s.mask[a];
            float sy = 0.f;
            while (msk) {
                int b = __ffs(msk) - 1;
                msk &= msk - 1;
                sy += s.T[b * KT + c];
            }
            s.Y1[i] = sy;
        }
        __syncthreads();

        // Y2[a][s] = sum_t Y1[a][k*10+t] * C2[k][s][t]  (C2 symmetric), then update
        {
            int c = tid & 127; c = tid % KT;       // column 0..159
            int half = tid / KT;                    // 0 or 1
            int k = c / MTt, ss = c - k * MTt;
            float c2r[MTt];
            #pragma unroll
            for (int t = 0; t < MTt; t++) c2r[t] = s.C2[k * (MTt * MTt) + ss * MTt + t];
            float cterm = s.cc[c];
            int aBeg = half ? 9 : 0;
            int aEnd = half ? Mm : 9;
            for (int a = aBeg; a < aEnd; a++) {
                const float* y1 = &s.Y1[a * KT + k * MTt];
                float y = 0.f;
                #pragma unroll
                for (int t = 0; t < MTt; t++) y += y1[t] * c2r[t];
                float gw = 2.f * (s.c1p[a] + cterm - 2.f * y);
                int idx = a * KT + c;
                s.lt[idx] -= coefA * gw + s.Mc[idx];
            }
        }
        __syncthreads();
    }

    // --- final T and marginal q -> output ---
    if (tid < Mm * NT) {
        int mi = tid >> 4, k = tid & 15;
        int base = mi * KT + k * MTt;
        float v[MTt];
        float mx = -1e30f;
        #pragma unroll
        for (int t = 0; t < MTt; t++) { v[t] = s.lt[base + t]; mx = fmaxf(mx, v[t]); }
        float ssum = 0.f;
        #pragma unroll
        for (int t = 0; t < MTt; t++) { float e = __expf(v[t] - mx); v[t] = e; ssum += e; }
        float inv = (1.f / (float)Mm) / ssum;
        #pragma unroll
        for (int t = 0; t < MTt; t++) s.T[base + t] = v[t] * inv;
    }
    __syncthreads();
    if (tid < KT) {
        float sq = 0.f;
        #pragma unroll
        for (int mi = 0; mi < Mm; mi++) sq += s.T[mi * KT + tid];
        out[(size_t)n * KT + tid] = sq;
    }
}

// ---------------------------------------------------------------------------
extern "C" void kernel_launch(void* const* d_in, const int* in_sizes, int n_in,
                              void* d_out, int out_size) {
    const float* x   = (const float*)d_in[0];
    const int*   ei  = (const int*)d_in[1];
    const float* C2g = (const float*)d_in[2];
    const float* F2  = (const float*)d_in[3];
    const float* a0  = (const float*)d_in[4];
    float* out = (float*)d_out;
    const int* dst = ei + Nn * DEG;   // edge_index row 1

    cudaFuncSetAttribute(gemm_kernel, cudaFuncAttributeMaxDynamicSharedMemorySize,
                         GEMM_SMEM);
    cudaFuncSetAttribute(main_kernel, cudaFuncAttributeMaxDynamicSharedMemorySize,
                         (int)sizeof(SmemMain));

    norms_kernel<<<(Nn + KT + 255) / 256, 256>>>(x, F2);
    gemm_kernel<<<Nn / GEMM_ROWS, 256, GEMM_SMEM>>>(x, F2);
    main_kernel<<<Nn, THREADS, sizeof(SmemMain)>>>(dst, C2g, a0, out);
}

// round 2
// speedup vs baseline: 1.2182x; 1.2182x over previous
#include <cuda_runtime.h>

#define Nn    6000
#define DEG   16
#define Mm    17          // DEG + 1
#define NT    16
#define MTt   10
#define NF    128
#define KT    160         // NT * MTt
#define PT    12          // padded per-template chunk (10 -> 12 for float4)
#define KTP   192         // NT * PT
#define NITER 10
#define THREADS 320
#define GEMM_ROWS 40
#define GEMM_SMEM ((KT * 129 + GEMM_ROWS * NF) * 4)

// Scratch (no allocations allowed): G = x @ F2^T, plus squared norms
__device__ float g_G[Nn * KT];
__device__ float g_xn[Nn];
__device__ float g_f2n[KT];

// ---------------------------------------------------------------------------
// packed f32x2 helpers (sm_103a)
// ---------------------------------------------------------------------------
__device__ __forceinline__ unsigned long long pk2(float lo, float hi) {
    unsigned long long r;
    asm("mov.b64 %0, {%1, %2};" : "=l"(r) : "f"(lo), "f"(hi));
    return r;
}
__device__ __forceinline__ void ffma2(unsigned long long& d,
                                      unsigned long long a, unsigned long long b) {
    asm("fma.rn.f32x2 %0, %1, %2, %0;" : "+l"(d) : "l"(a), "l"(b));
}
__device__ __forceinline__ float hadd2(unsigned long long v) {
    float lo, hi;
    asm("mov.b64 {%0, %1}, %2;" : "=f"(lo), "=f"(hi) : "l"(v));
    return lo + hi;
}
// dot of 12 contiguous smem floats (pads zero) with 6 packed f32x2 coeffs
__device__ __forceinline__ float dot12(const float* p, const unsigned long long* cp) {
    float4 v0 = *(const float4*)(p);
    float4 v1 = *(const float4*)(p + 4);
    float4 v2 = *(const float4*)(p + 8);
    unsigned long long acc = 0ULL;
    ffma2(acc, pk2(v0.x, v0.y), cp[0]);
    ffma2(acc, pk2(v0.z, v0.w), cp[1]);
    ffma2(acc, pk2(v1.x, v1.y), cp[2]);
    ffma2(acc, pk2(v1.z, v1.w), cp[3]);
    ffma2(acc, pk2(v2.x, v2.y), cp[4]);
    ffma2(acc, pk2(v2.z, v2.w), cp[5]);
    return hadd2(acc);
}

// ---------------------------------------------------------------------------
// Kernel 1: G[n][kt] = sum_f x[n][f] * F2[kt][f]  (+ fused row norms)
// ---------------------------------------------------------------------------
__global__ __launch_bounds__(256, 2)
void gemm_kernel(const float* __restrict__ x, const float* __restrict__ F2) {
    extern __shared__ float sm[];
    float* sF2 = sm;                 // 160 x 129
    float* sX  = sm + KT * 129;      // 40 x 128
    int tid = threadIdx.x;
    int r0 = blockIdx.x * GEMM_ROWS;

    for (int i = tid; i < KT * NF; i += 256) {
        int r = i >> 7, f = i & 127;
        sF2[r * 129 + f] = F2[i];
    }
    for (int i = tid; i < GEMM_ROWS * NF; i += 256)
        sX[i] = x[(size_t)r0 * NF + i];
    __syncthreads();

    // fused norms
    if (tid < GEMM_ROWS) {
        float s = 0.f;
        #pragma unroll 8
        for (int f = 0; f < NF; f++) { float v = sX[tid * NF + f]; s += v * v; }
        g_xn[r0 + tid] = s;
    }
    if (blockIdx.x == 0 && tid >= 64 && tid < 64 + KT) {
        int r = tid - 64;
        float s = 0.f;
        #pragma unroll 8
        for (int f = 0; f < NF; f++) { float v = sF2[r * 129 + f]; s += v * v; }
        g_f2n[r] = s;
    }

    int tm = tid >> 5;   // 0..7  -> 5 rows each
    int tn = tid & 31;   // 0..31 -> 5 cols each
    float acc[5][5];
    #pragma unroll
    for (int i = 0; i < 5; i++)
        #pragma unroll
        for (int j = 0; j < 5; j++) acc[i][j] = 0.f;

    for (int f = 0; f < NF; f++) {
        float av[5], bv[5];
        #pragma unroll
        for (int i = 0; i < 5; i++) av[i] = sX[(tm * 5 + i) * NF + f];
        #pragma unroll
        for (int j = 0; j < 5; j++) bv[j] = sF2[(tn * 5 + j) * 129 + f];
        #pragma unroll
        for (int i = 0; i < 5; i++)
            #pragma unroll
            for (int j = 0; j < 5; j++) acc[i][j] += av[i] * bv[j];
    }
    #pragma unroll
    for (int i = 0; i < 5; i++) {
        int row = r0 + tm * 5 + i;
        #pragma unroll
        for (int j = 0; j < 5; j++)
            g_G[(size_t)row * KT + tn * 5 + j] = acc[i][j];
    }
}

// ---------------------------------------------------------------------------
// Kernel 2: main mirror-descent. One block per node, 320 threads.
// Padded layout: chunk for template k at offset k*12 (10 used, 2 zero pads).
// ---------------------------------------------------------------------------
struct SmemMain {
    float lt [Mm * KTP];   // 3264
    float T  [Mm * KTP];
    float Y1 [Mm * KTP];   // rows 1..16 only
    float McB[Mm * KTP];   // coefM*Mcost + 2*coefA*c1p   (iteration-invariant)
    float q  [KTP];
    float c1p[Mm];
    float xnl[Mm];
    int   nbrs[Mm];
    int   dstl[Mm * DEG];
    unsigned mask[Mm];
};

__global__ __launch_bounds__(THREADS, 4)
void main_kernel(const int* __restrict__ dst, const float* __restrict__ C2g,
                 const float* __restrict__ alpha0, float* __restrict__ out) {
    extern __shared__ char smraw[];
    SmemMain& s = *reinterpret_cast<SmemMain*>(smraw);
    int n = blockIdx.x, tid = threadIdx.x;

    float a0 = alpha0[0];
    float alpha = 1.f / (1.f + __expf(-a0));
    float coefA = alpha * 10.f;            // alpha / REG
    float coefM = (1.f - alpha) * 10.f;    // (1-alpha) / REG
    float cA2 = 2.f * coefA, cA4 = 4.f * coefA;

    // --- neighbor list ---
    if (tid < Mm) s.nbrs[tid] = (tid == 0) ? n : dst[n * DEG + tid - 1];
    // zero lt (also zeroes pads)
    for (int i = tid; i < Mm * KTP; i += THREADS) s.lt[i] = 0.f;
    __syncthreads();

    if (tid < Mm * DEG)
        s.dstl[tid] = dst[s.nbrs[tid >> 4] * DEG + (tid & 15)];
    __syncthreads();

    // --- adjacency bitmask ---
    if (tid < Mm) {
        int me = s.nbrs[tid];
        unsigned mrow = 0;
        for (int b = 0; b < Mm; b++) {
            int nb = s.nbrs[b];
            bool adj = false;
            #pragma unroll
            for (int j = 0; j < DEG; j++)
                adj = adj || (s.dstl[tid * DEG + j] == nb) ||
                             (s.dstl[b   * DEG + j] == me);
            if (adj) mrow |= (1u << b);
        }
        s.mask[tid] = mrow;
        s.c1p[tid]  = (float)__popc(mrow) * (1.f / (float)Mm);  // C1^2=C1, p=1/17
        s.xnl[tid]  = g_xn[s.nbrs[tid]];
    }
    __syncthreads();

    // --- column-thread persistent state: packed C2 row + C2^2 row ---
    int ck = 0, c12 = 0;
    unsigned long long c2p[6], c2sqp[6];
    if (tid < KT) {
        ck = tid / MTt;
        int cs = tid - ck * MTt;
        c12 = ck * PT + cs;
        const float* c2 = C2g + (ck * MTt + cs) * MTt;
        #pragma unroll
        for (int i = 0; i < 5; i++) {
            float a = c2[2 * i], b = c2[2 * i + 1];
            c2p[i]   = pk2(a, b);
            c2sqp[i] = pk2(a * a, b * b);
        }
        c2p[5] = 0ULL; c2sqp[5] = 0ULL;

        // McB in smem (padded layout)
        float f2 = g_f2n[tid];
        #pragma unroll
        for (int a = 0; a < Mm; a++) {
            int row = s.nbrs[a];
            float dot = g_G[(size_t)row * KT + tid];
            s.McB[a * KTP + c12] = coefM * (s.xnl[a] + f2 - 2.f * dot)
                                 + cA2 * s.c1p[a];
        }
    }
    __syncthreads();

    // --- 10 mirror-descent iterations ---
    for (int it = 0; it < NITER; it++) {
        // A) softmax over t (max subtract in registers only; T pads = 0)
        if (tid < Mm * NT) {
            int mi = tid >> 4, kk = tid & 15;
            const float* base = &s.lt[mi * KTP + kk * PT];
            float4 v0 = *(const float4*)(base);
            float4 v1 = *(const float4*)(base + 4);
            float4 v2 = *(const float4*)(base + 8);
            float e[10] = {v0.x, v0.y, v0.z, v0.w, v1.x, v1.y, v1.z, v1.w, v2.x, v2.y};
            float mx = e[0];
            #pragma unroll
            for (int t = 1; t < MTt; t++) mx = fmaxf(mx, e[t]);
            float ssum = 0.f;
            #pragma unroll
            for (int t = 0; t < MTt; t++) { e[t] = __expf(e[t] - mx); ssum += e[t]; }
            float inv = (1.f / (float)Mm) / ssum;
            float* tb = &s.T[mi * KTP + kk * PT];
            *(float4*)(tb)     = make_float4(e[0]*inv, e[1]*inv, e[2]*inv, e[3]*inv);
            *(float4*)(tb + 4) = make_float4(e[4]*inv, e[5]*inv, e[6]*inv, e[7]*inv);
            *(float4*)(tb + 8) = make_float4(e[8]*inv, e[9]*inv, 0.f, 0.f);
        }
        __syncthreads();

        // B1) q = column sums of T (48 threads, vectorized)
        if (tid < 48) {
            int kk = tid / 3, j4 = (tid - kk * 3) * 4;
            int off = kk * PT + j4;
            float4 acc = make_float4(0.f, 0.f, 0.f, 0.f);
            #pragma unroll
            for (int m = 0; m < Mm; m++) {
                float4 t = *(const float4*)&s.T[m * KTP + off];
                acc.x += t.x; acc.y += t.y; acc.z += t.z; acc.w += t.w;
            }
            *(float4*)&s.q[off] = acc;
        }
        // B2) Y1 rows 1..16 (sparse masked gather, float4 over columns)
        for (int tau = tid; tau < 16 * 48; tau += THREADS) {
            int a = 1 + tau / 48;
            int rem = tau - (a - 1) * 48;
            int kk = rem / 3, j4 = (rem - kk * 3) * 4;
            int off = kk * PT + j4;
            unsigned msk = s.mask[a];
            float4 acc = make_float4(0.f, 0.f, 0.f, 0.f);
            while (msk) {
                int b = __ffs(msk) - 1;
                msk &= msk - 1;
                float4 t = *(const float4*)&s.T[b * KTP + off];
                acc.x += t.x; acc.y += t.y; acc.z += t.z; acc.w += t.w;
            }
            *(float4*)&s.Y1[a * KTP + off] = acc;
        }
        __syncthreads();

        // C) Y2 + lt update (column threads). cc and row-0 come from q.
        if (tid < KT) {
            const float* qp = &s.q[ck * PT];
            float cc = dot12(qp, c2sqp);           // constC2[k][s]
            float y0 = dot12(qp, c2p);             // Y2 row 0 via complement
            unsigned cm = (~s.mask[0]) & 0x1FFFFu;
            while (cm) {
                int b = __ffs(cm) - 1;
                cm &= cm - 1;
                y0 -= dot12(&s.T[b * KTP + ck * PT], c2p);
            }
            float ccterm = cA2 * cc;
            {
                float ltv = s.lt[c12];
                s.lt[c12] = ltv - s.McB[c12] - ccterm + cA4 * y0;
            }
            #pragma unroll
            for (int a = 1; a < Mm; a++) {
                float y = dot12(&s.Y1[a * KTP + ck * PT], c2p);
                int idx = a * KTP + c12;
                s.lt[idx] = s.lt[idx] - s.McB[idx] - ccterm + cA4 * y;
            }
        }
        __syncthreads();
    }

    // --- final T and marginal q -> output ---
    if (tid < Mm * NT) {
        int mi = tid >> 4, kk = tid & 15;
        const float* base = &s.lt[mi * KTP + kk * PT];
        float4 v0 = *(const float4*)(base);
        float4 v1 = *(const float4*)(base + 4);
        float4 v2 = *(const float4*)(base + 8);
        float e[10] = {v0.x, v0.y, v0.z, v0.w, v1.x, v1.y, v1.z, v1.w, v2.x, v2.y};
        float mx = e[0];
        #pragma unroll
        for (int t = 1; t < MTt; t++) mx = fmaxf(mx, e[t]);
        float ssum = 0.f;
        #pragma unroll
        for (int t = 0; t < MTt; t++) { e[t] = __expf(e[t] - mx); ssum += e[t]; }
        float inv = (1.f / (float)Mm) / ssum;
        float* tb = &s.T[mi * KTP + kk * PT];
        *(float4*)(tb)     = make_float4(e[0]*inv, e[1]*inv, e[2]*inv, e[3]*inv);
        *(float4*)(tb + 4) = make_float4(e[4]*inv, e[5]*inv, e[6]*inv, e[7]*inv);
        *(float4*)(tb + 8) = make_float4(e[8]*inv, e[9]*inv, 0.f, 0.f);
    }
    __syncthreads();
    if (tid < KT) {
        float sq = 0.f;
        #pragma unroll
        for (int m = 0; m < Mm; m++) sq += s.T[m * KTP + c12];
        out[(size_t)n * KT + tid] = sq;
    }
}

// ---------------------------------------------------------------------------
extern "C" void kernel_launch(void* const* d_in, const int* in_sizes, int n_in,
                              void* d_out, int out_size) {
    const float* x   = (const float*)d_in[0];
    const int*   ei  = (const int*)d_in[1];
    const float* C2g = (const float*)d_in[2];
    const float* F2  = (const float*)d_in[3];
    const float* a0  = (const float*)d_in[4];
    float* out = (float*)d_out;
    const int* dst = ei + Nn * DEG;   // edge_index row 1

    cudaFuncSetAttribute(gemm_kernel, cudaFuncAttributeMaxDynamicSharedMemorySize,
                         GEMM_SMEM);
    cudaFuncSetAttribute(main_kernel, cudaFuncAttributeMaxDynamicSharedMemorySize,
                         (int)sizeof(SmemMain));

    gemm_kernel<<<Nn / GEMM_ROWS, 256, GEMM_SMEM>>>(x, F2);
    main_kernel<<<Nn, THREADS, sizeof(SmemMain)>>>(dst, C2g, a0, out);
}